// round 3
// baseline (speedup 1.0000x reference)
#include <cuda_runtime.h>

#define NN 50000
#define EE 800000
#define HH 64
#define CC 10
#define SCAN_BLK 250
#define SCAN_PER 200   // 250 * 200 = 50000

// Scratch (allocation-free: __device__ globals)
__device__ int g_stride;           // 1 if edge_index int32, 2 if int64 (low word)
__device__ int g_degi[NN];         // out-degree by src (normalization)
__device__ int g_cnt[NN];          // in-degree by dst (CSR row lengths)
__device__ int g_rowstart[NN];     // CSR row offsets
__device__ int g_next[NN];         // fill cursors
__device__ int g_bsum[SCAN_BLK];
__device__ int g_srcs[EE];         // CSR column (src) indices, grouped by dst
__device__ float g_dis[NN];
__device__ __align__(16) float g_h[NN * HH];
__device__ __align__(16) float g_hs[NN * HH];   // dis[i] * h[i]
__device__ __align__(16) float g_lap[NN * HH];

// ---------------------------------------------------------------------------
// Detect edge_index dtype (parallel). int64 values in [0,50000) => odd 32-bit
// words all zero (little-endian). 32 random int32 indices all zero: ~impossible.
// ---------------------------------------------------------------------------
__global__ void k_detect(const int* __restrict__ p) {
    int t = threadIdx.x;  // 32 threads
    int bad = (p[2 * t + 1] != 0);
    unsigned b = __ballot_sync(0xffffffffu, bad);
    if (t == 0) g_stride = (b == 0u) ? 2 : 1;
}

// ---------------------------------------------------------------------------
// Zero histograms (lap is fully overwritten by gather; no zeroing needed)
// ---------------------------------------------------------------------------
__global__ __launch_bounds__(256) void k_zero() {
    int i = blockIdx.x * 256 + threadIdx.x;
    int stride = gridDim.x * 256;
    for (int j = i; j < NN; j += stride) {
        g_degi[j] = 0;
        g_cnt[j] = 0;
    }
}

// ---------------------------------------------------------------------------
// One pass: src out-degree + dst in-degree
// ---------------------------------------------------------------------------
__global__ __launch_bounds__(256) void k_hist(const int* __restrict__ ei) {
    int e = blockIdx.x * 256 + threadIdx.x;
    if (e < EE) {
        int st = g_stride;
        int s = __ldg(&ei[e * st]);
        int d = __ldg(&ei[(EE + e) * st]);
        atomicAdd(&g_degi[s], 1);
        atomicAdd(&g_cnt[d], 1);
    }
}

// ---------------------------------------------------------------------------
__global__ __launch_bounds__(256) void k_dis() {
    int i = blockIdx.x * 256 + threadIdx.x;
    if (i < NN) {
        int d = g_degi[i];
        g_dis[i] = (d > 0) ? rsqrtf((float)d) : 0.f;
    }
}

// ---------------------------------------------------------------------------
// 3-phase exclusive scan of g_cnt -> g_rowstart (and g_next copy)
// ---------------------------------------------------------------------------
__global__ __launch_bounds__(256) void k_scan1() {
    __shared__ int sh[256];
    int t = threadIdx.x, b = blockIdx.x;
    sh[t] = (t < SCAN_PER) ? g_cnt[b * SCAN_PER + t] : 0;
    __syncthreads();
    for (int off = 128; off > 0; off >>= 1) {
        if (t < off) sh[t] += sh[t + off];
        __syncthreads();
    }
    if (t == 0) g_bsum[b] = sh[0];
}

__global__ __launch_bounds__(256) void k_scan2() {
    __shared__ int sh[SCAN_BLK];
    int t = threadIdx.x;
    if (t < SCAN_BLK) sh[t] = g_bsum[t];
    __syncthreads();
    if (t == 0) {
        int run = 0;
        for (int i = 0; i < SCAN_BLK; i++) { int v = sh[i]; sh[i] = run; run += v; }
    }
    __syncthreads();
    if (t < SCAN_BLK) g_bsum[t] = sh[t];
}

__global__ __launch_bounds__(256) void k_scan3() {
    __shared__ int sh[SCAN_PER];
    int t = threadIdx.x, b = blockIdx.x;
    if (t < SCAN_PER) sh[t] = g_cnt[b * SCAN_PER + t];
    __syncthreads();
    if (t == 0) {
        int run = g_bsum[b];
        for (int i = 0; i < SCAN_PER; i++) { int v = sh[i]; sh[i] = run; run += v; }
    }
    __syncthreads();
    if (t < SCAN_PER) {
        int i = b * SCAN_PER + t;
        g_rowstart[i] = sh[t];
        g_next[i] = sh[t];
    }
}

// ---------------------------------------------------------------------------
// Bucket fill: group src indices by dst
// ---------------------------------------------------------------------------
__global__ __launch_bounds__(256) void k_fill(const int* __restrict__ ei) {
    int e = blockIdx.x * 256 + threadIdx.x;
    if (e < EE) {
        int st = g_stride;
        int s = __ldg(&ei[e * st]);
        int d = __ldg(&ei[(EE + e) * st]);
        int pos = atomicAdd(&g_next[d], 1);
        g_srcs[pos] = s;
    }
}

// ---------------------------------------------------------------------------
// h = relu(x @ W1 + b1); hs = dis[row] * h   (warp per row, W1 in smem)
// ---------------------------------------------------------------------------
__global__ __launch_bounds__(256) void k_gemm1(const float* __restrict__ x,
                                               const float* __restrict__ W1,
                                               const float* __restrict__ b1) {
    __shared__ float Ws[HH * HH];
    __shared__ float xs[8][HH];
    for (int i = threadIdx.x; i < HH * HH; i += 256) Ws[i] = W1[i];
    __syncthreads();

    int warp = threadIdx.x >> 5;
    int lane = threadIdx.x & 31;
    int row = blockIdx.x * 8 + warp;
    if (row >= NN) return;

    xs[warp][lane]      = x[row * HH + lane];
    xs[warp][lane + 32] = x[row * HH + lane + 32];
    __syncwarp();

    float a0 = b1[lane];
    float a1 = b1[lane + 32];
#pragma unroll
    for (int k = 0; k < HH; k++) {
        float xv = xs[warp][k];
        a0 = fmaf(xv, Ws[k * HH + lane],      a0);
        a1 = fmaf(xv, Ws[k * HH + lane + 32], a1);
    }
    a0 = fmaxf(a0, 0.f);
    a1 = fmaxf(a1, 0.f);
    float sc = g_dis[row];
    g_h[row * HH + lane]       = a0;
    g_h[row * HH + lane + 32]  = a1;
    g_hs[row * HH + lane]      = sc * a0;
    g_hs[row * HH + lane + 32] = sc * a1;
}

// ---------------------------------------------------------------------------
// CSR gather: lap[d] = -dis[d] * sum_{e in row d} hs[src[e]]
// Warp per row, lane covers features {2*lane, 2*lane+1} (float2).
// ---------------------------------------------------------------------------
__global__ __launch_bounds__(256) void k_gather() {
    int warp = (blockIdx.x * 256 + threadIdx.x) >> 5;
    int lane = threadIdx.x & 31;
    if (warp >= NN) return;
    int row = warp;

    int start = g_rowstart[row];
    int len = g_cnt[row];

    float ax = 0.f, ay = 0.f;
    for (int base = 0; base < len; base += 32) {
        int j = base + lane;
        int s = (j < len) ? __ldg(&g_srcs[start + j]) : 0;
        int m = min(32, len - base);
        for (int jj = 0; jj < m; jj++) {
            int sj = __shfl_sync(0xffffffffu, s, jj);
            float2 v = __ldg((const float2*)&g_hs[sj * HH + lane * 2]);
            ax += v.x;
            ay += v.y;
        }
    }
    float sc = -g_dis[row];
    ((float2*)g_lap)[row * 32 + lane] = make_float2(ax * sc, ay * sc);
}

// ---------------------------------------------------------------------------
// Fused: h2 = relu(h@W20 + lap@W21 + b2); o = (h2+h)@Wl + bl; log_softmax
// ---------------------------------------------------------------------------
__global__ __launch_bounds__(256) void k_final(const float* __restrict__ W20,
                                               const float* __restrict__ W21,
                                               const float* __restrict__ b2,
                                               const float* __restrict__ Wl,
                                               const float* __restrict__ bl,
                                               float* __restrict__ out) {
    __shared__ float W20s[HH * HH];
    __shared__ float W21s[HH * HH];
    __shared__ float Wls[HH * CC];
    __shared__ float hs[8][HH];
    __shared__ float ls[8][HH];

    for (int i = threadIdx.x; i < HH * HH; i += 256) {
        W20s[i] = W20[i];
        W21s[i] = W21[i];
    }
    for (int i = threadIdx.x; i < HH * CC; i += 256) Wls[i] = Wl[i];
    __syncthreads();

    int warp = threadIdx.x >> 5;
    int lane = threadIdx.x & 31;
    int row = blockIdx.x * 8 + warp;
    if (row >= NN) return;

    hs[warp][lane]      = g_h[row * HH + lane];
    hs[warp][lane + 32] = g_h[row * HH + lane + 32];
    ls[warp][lane]      = g_lap[row * HH + lane];
    ls[warp][lane + 32] = g_lap[row * HH + lane + 32];
    __syncwarp();

    float a0 = b2[lane];
    float a1 = b2[lane + 32];
#pragma unroll
    for (int k = 0; k < HH; k++) {
        float hv = hs[warp][k];
        float lv = ls[warp][k];
        a0 = fmaf(hv, W20s[k * HH + lane],      a0);
        a0 = fmaf(lv, W21s[k * HH + lane],      a0);
        a1 = fmaf(hv, W20s[k * HH + lane + 32], a1);
        a1 = fmaf(lv, W21s[k * HH + lane + 32], a1);
    }
    float s0 = fmaxf(a0, 0.f) + hs[warp][lane];
    float s1 = fmaxf(a1, 0.f) + hs[warp][lane + 32];

    float p[CC];
#pragma unroll
    for (int c = 0; c < CC; c++)
        p[c] = fmaf(s0, Wls[lane * CC + c], s1 * Wls[(lane + 32) * CC + c]);

#pragma unroll
    for (int off = 16; off > 0; off >>= 1) {
#pragma unroll
        for (int c = 0; c < CC; c++)
            p[c] += __shfl_xor_sync(0xffffffffu, p[c], off);
    }

    if (lane == 0) {
        float m = -1e30f;
#pragma unroll
        for (int c = 0; c < CC; c++) {
            p[c] += bl[c];
            m = fmaxf(m, p[c]);
        }
        float sum = 0.f;
#pragma unroll
        for (int c = 0; c < CC; c++) sum += expf(p[c] - m);
        float lse = logf(sum);
#pragma unroll
        for (int c = 0; c < CC; c++) out[row * CC + c] = p[c] - m - lse;
    }
}

// ---------------------------------------------------------------------------
extern "C" void kernel_launch(void* const* d_in, const int* in_sizes, int n_in,
                              void* d_out, int out_size) {
    const float* x   = (const float*)d_in[0];
    const int*   ei  = (const int*)d_in[1];
    const float* W1  = (const float*)d_in[2];
    const float* b1  = (const float*)d_in[3];
    const float* W20 = (const float*)d_in[4];
    const float* W21 = (const float*)d_in[5];
    const float* b2  = (const float*)d_in[6];
    const float* Wl  = (const float*)d_in[7];
    const float* bl  = (const float*)d_in[8];
    float* out = (float*)d_out;

    k_detect<<<1, 32>>>(ei);
    k_zero<<<64, 256>>>();
    k_hist<<<(EE + 255) / 256, 256>>>(ei);
    k_dis<<<(NN + 255) / 256, 256>>>();
    k_scan1<<<SCAN_BLK, 256>>>();
    k_scan2<<<1, 256>>>();
    k_scan3<<<SCAN_BLK, 256>>>();
    k_fill<<<(EE + 255) / 256, 256>>>(ei);
    k_gemm1<<<(NN + 7) / 8, 256>>>(x, W1, b1);
    k_gather<<<(NN * 32 + 255) / 256, 256>>>();
    k_final<<<(NN + 7) / 8, 256>>>(W20, W21, b2, Wl, bl, out);
}

// round 4
// speedup vs baseline: 1.1821x; 1.1821x over previous
#include <cuda_runtime.h>

#define NN 50000
#define EE 800000
#define HH 64
#define CC 10
#define CHUNK 200
#define NCHUNK 250   // 250 * 200 = 50000

// Scratch (allocation-free: __device__ globals)
__device__ int g_stride;           // 1 if edge_index int32, 2 if int64 (low word)
__device__ int g_degi[NN];         // out-degree by src
__device__ int g_cnt[NN];          // in-degree by dst (CSR row lengths)
__device__ int g_rowstart[NN];     // CSR row offsets
__device__ int g_next[NN];         // fill cursors
__device__ int g_bsum[NCHUNK];
__device__ int g_srcs[EE];         // CSR column (src) indices grouped by dst
__device__ float g_dis[NN];
__device__ __align__(16) float g_h[NN * HH];
__device__ __align__(16) float g_hs[NN * HH];   // dis[i] * h[i]
__device__ __align__(16) float g_lap[NN * HH];

// ---------------------------------------------------------------------------
// Launch 0: dtype detect (block 0, warp 0) + zero histograms (all blocks)
// ---------------------------------------------------------------------------
__global__ __launch_bounds__(256) void k_pre(const int* __restrict__ p) {
    if (blockIdx.x == 0 && threadIdx.x < 32) {
        int t = threadIdx.x;
        int bad = (p[2 * t + 1] != 0);
        unsigned b = __ballot_sync(0xffffffffu, bad);
        if (t == 0) g_stride = (b == 0u) ? 2 : 1;
    }
    int i = blockIdx.x * 256 + threadIdx.x;
    int stride = gridDim.x * 256;
    for (int j = i; j < NN; j += stride) {
        g_degi[j] = 0;
        g_cnt[j] = 0;
    }
}

// ---------------------------------------------------------------------------
// Launch 1: src out-degree + dst in-degree in one pass
// ---------------------------------------------------------------------------
__global__ __launch_bounds__(256) void k_hist(const int* __restrict__ ei) {
    int e = blockIdx.x * 256 + threadIdx.x;
    if (e < EE) {
        int st = g_stride;
        int s = __ldg(&ei[e * st]);
        int d = __ldg(&ei[(EE + e) * st]);
        atomicAdd(&g_degi[s], 1);
        atomicAdd(&g_cnt[d], 1);
    }
}

// ---------------------------------------------------------------------------
// Launch 2: per-chunk sums of cnt -> g_bsum  +  dis = rsqrt(degi)
// ---------------------------------------------------------------------------
__global__ __launch_bounds__(256) void k_scanA() {
    __shared__ int sh[256];
    int t = threadIdx.x, b = blockIdx.x;
    int i = b * CHUNK + t;
    sh[t] = (t < CHUNK) ? g_cnt[i] : 0;
    __syncthreads();
#pragma unroll
    for (int off = 128; off > 0; off >>= 1) {
        if (t < off) sh[t] += sh[t + off];
        __syncthreads();
    }
    if (t == 0) g_bsum[b] = sh[0];
    if (t < CHUNK) {
        int d = g_degi[i];
        g_dis[i] = (d > 0) ? rsqrtf((float)d) : 0.f;
    }
}

// ---------------------------------------------------------------------------
// Launch 3 (fused): blocks [0,250): finish the scan (rowstart/next)
//                   blocks [250,...): GEMM1  h = relu(x@W1+b1); hs = dis*h
// GEMM1: 32 rows/block (8 warps x 4 rows), lane owns columns {2l, 2l+1}
// ---------------------------------------------------------------------------
__global__ __launch_bounds__(256) void k_scanB_gemm1(const float* __restrict__ x,
                                                     const float* __restrict__ W1,
                                                     const float* __restrict__ b1) {
    __shared__ float Ws[HH * HH];      // 16 KB (gemm role)
    __shared__ float xs[8][HH];        //  2 KB (gemm role)
    __shared__ int bs[256];            // scan role
    __shared__ int cs[256];            // scan role

    if (blockIdx.x < NCHUNK) {
        int t = threadIdx.x, b = blockIdx.x;
        bs[t] = (t < NCHUNK) ? g_bsum[t] : 0;
        __syncthreads();
#pragma unroll
        for (int off = 1; off < 256; off <<= 1) {
            int add = (t >= off) ? bs[t - off] : 0;
            __syncthreads();
            bs[t] += add;
            __syncthreads();
        }
        int base = (b > 0) ? bs[b - 1] : 0;
        int i = b * CHUNK + t;
        int c = (t < CHUNK) ? g_cnt[i] : 0;
        cs[t] = c;
        __syncthreads();
#pragma unroll
        for (int off = 1; off < 256; off <<= 1) {
            int add = (t >= off) ? cs[t - off] : 0;
            __syncthreads();
            cs[t] += add;
            __syncthreads();
        }
        if (t < CHUNK) {
            int rs = base + cs[t] - c;
            g_rowstart[i] = rs;
            g_next[i] = rs;
        }
        return;
    }

    // ---- GEMM1 role ----
    for (int i = threadIdx.x; i < HH * HH; i += 256) Ws[i] = W1[i];
    __syncthreads();

    int warp = threadIdx.x >> 5;
    int lane = threadIdx.x & 31;
    int rowbase = (blockIdx.x - NCHUNK) * 32 + warp * 4;
    float bx = b1[2 * lane], by = b1[2 * lane + 1];

#pragma unroll 1
    for (int r = 0; r < 4; r++) {
        int row = rowbase + r;
        if (row >= NN) break;
        xs[warp][lane]      = x[row * HH + lane];
        xs[warp][lane + 32] = x[row * HH + lane + 32];
        __syncwarp();

        float ax = bx, ay = by;
#pragma unroll
        for (int k = 0; k < HH; k += 2) {
            float2 xv = *(const float2*)&xs[warp][k];
            float2 w0 = *(const float2*)&Ws[k * HH + 2 * lane];
            float2 w1 = *(const float2*)&Ws[(k + 1) * HH + 2 * lane];
            ax = fmaf(xv.x, w0.x, ax); ay = fmaf(xv.x, w0.y, ay);
            ax = fmaf(xv.y, w1.x, ax); ay = fmaf(xv.y, w1.y, ay);
        }
        ax = fmaxf(ax, 0.f); ay = fmaxf(ay, 0.f);
        float sc = g_dis[row];
        ((float2*)g_h)[row * 32 + lane]  = make_float2(ax, ay);
        ((float2*)g_hs)[row * 32 + lane] = make_float2(sc * ax, sc * ay);
        __syncwarp();
    }
}

// ---------------------------------------------------------------------------
// Launch 4: bucket fill (group src indices by dst)
// ---------------------------------------------------------------------------
__global__ __launch_bounds__(256) void k_fill(const int* __restrict__ ei) {
    int e = blockIdx.x * 256 + threadIdx.x;
    if (e < EE) {
        int st = g_stride;
        int s = __ldg(&ei[e * st]);
        int d = __ldg(&ei[(EE + e) * st]);
        int pos = atomicAdd(&g_next[d], 1);
        g_srcs[pos] = s;
    }
}

// ---------------------------------------------------------------------------
// Launch 5: CSR gather  lap[d] = -dis[d] * sum hs[src]
// Warp per row; lane covers features {2l, 2l+1} (float2, coalesced rows)
// ---------------------------------------------------------------------------
__global__ __launch_bounds__(256) void k_gather() {
    int row = (blockIdx.x * 256 + threadIdx.x) >> 5;
    int lane = threadIdx.x & 31;
    if (row >= NN) return;

    int start = g_rowstart[row];
    int len = g_cnt[row];

    float ax = 0.f, ay = 0.f;
    for (int base = 0; base < len; base += 32) {
        int j = base + lane;
        int s = (j < len) ? __ldg(&g_srcs[start + j]) : 0;
        int m = min(32, len - base);
#pragma unroll 4
        for (int jj = 0; jj < m; jj++) {
            int sj = __shfl_sync(0xffffffffu, s, jj);
            float2 v = __ldg((const float2*)&g_hs[sj * HH + 2 * lane]);
            ax += v.x;
            ay += v.y;
        }
    }
    float sc = -g_dis[row];
    ((float2*)g_lap)[row * 32 + lane] = make_float2(ax * sc, ay * sc);
}

// ---------------------------------------------------------------------------
// Launch 6: fused  h2 = relu(h@W20 + lap@W21 + b2);
//           o = (h2+h)@Wl + bl; log_softmax.  32 rows/block.
// ---------------------------------------------------------------------------
__global__ __launch_bounds__(256) void k_final(const float* __restrict__ W20,
                                               const float* __restrict__ W21,
                                               const float* __restrict__ b2,
                                               const float* __restrict__ Wl,
                                               const float* __restrict__ bl,
                                               float* __restrict__ out) {
    __shared__ float W20s[HH * HH];
    __shared__ float W21s[HH * HH];
    __shared__ float Wls[HH * CC];
    __shared__ float hs[8][HH];
    __shared__ float ls[8][HH];

    for (int i = threadIdx.x; i < HH * HH; i += 256) {
        W20s[i] = W20[i];
        W21s[i] = W21[i];
    }
    for (int i = threadIdx.x; i < HH * CC; i += 256) Wls[i] = Wl[i];
    __syncthreads();

    int warp = threadIdx.x >> 5;
    int lane = threadIdx.x & 31;
    int rowbase = blockIdx.x * 32 + warp * 4;
    float b2x = b2[2 * lane], b2y = b2[2 * lane + 1];

#pragma unroll 1
    for (int r = 0; r < 4; r++) {
        int row = rowbase + r;
        if (row >= NN) break;

        hs[warp][lane]      = g_h[row * HH + lane];
        hs[warp][lane + 32] = g_h[row * HH + lane + 32];
        ls[warp][lane]      = g_lap[row * HH + lane];
        ls[warp][lane + 32] = g_lap[row * HH + lane + 32];
        __syncwarp();

        float ax = b2x, ay = b2y;
#pragma unroll
        for (int k = 0; k < HH; k += 2) {
            float2 hv = *(const float2*)&hs[warp][k];
            float2 lv = *(const float2*)&ls[warp][k];
            float2 w0a = *(const float2*)&W20s[k * HH + 2 * lane];
            float2 w1a = *(const float2*)&W21s[k * HH + 2 * lane];
            float2 w0b = *(const float2*)&W20s[(k + 1) * HH + 2 * lane];
            float2 w1b = *(const float2*)&W21s[(k + 1) * HH + 2 * lane];
            ax = fmaf(hv.x, w0a.x, ax); ay = fmaf(hv.x, w0a.y, ay);
            ax = fmaf(lv.x, w1a.x, ax); ay = fmaf(lv.x, w1a.y, ay);
            ax = fmaf(hv.y, w0b.x, ax); ay = fmaf(hv.y, w0b.y, ay);
            ax = fmaf(lv.y, w1b.x, ax); ay = fmaf(lv.y, w1b.y, ay);
        }
        float s0 = fmaxf(ax, 0.f) + hs[warp][2 * lane];
        float s1 = fmaxf(ay, 0.f) + hs[warp][2 * lane + 1];

        float p[CC];
#pragma unroll
        for (int c = 0; c < CC; c++)
            p[c] = fmaf(s0, Wls[2 * lane * CC + c], s1 * Wls[(2 * lane + 1) * CC + c]);

#pragma unroll
        for (int off = 16; off > 0; off >>= 1) {
#pragma unroll
            for (int c = 0; c < CC; c++)
                p[c] += __shfl_xor_sync(0xffffffffu, p[c], off);
        }

        if (lane == 0) {
            float m = -1e30f;
#pragma unroll
            for (int c = 0; c < CC; c++) {
                p[c] += bl[c];
                m = fmaxf(m, p[c]);
            }
            float sum = 0.f;
#pragma unroll
            for (int c = 0; c < CC; c++) sum += expf(p[c] - m);
            float lse = logf(sum);
#pragma unroll
            for (int c = 0; c < CC; c++) out[row * CC + c] = p[c] - m - lse;
        }
        __syncwarp();
    }
}

// ---------------------------------------------------------------------------
extern "C" void kernel_launch(void* const* d_in, const int* in_sizes, int n_in,
                              void* d_out, int out_size) {
    const float* x   = (const float*)d_in[0];
    const int*   ei  = (const int*)d_in[1];
    const float* W1  = (const float*)d_in[2];
    const float* b1  = (const float*)d_in[3];
    const float* W20 = (const float*)d_in[4];
    const float* W21 = (const float*)d_in[5];
    const float* b2  = (const float*)d_in[6];
    const float* Wl  = (const float*)d_in[7];
    const float* bl  = (const float*)d_in[8];
    float* out = (float*)d_out;

    k_pre<<<64, 256>>>(ei);                                   // 0
    k_hist<<<(EE + 255) / 256, 256>>>(ei);                    // 1
    k_scanA<<<NCHUNK, 256>>>();                               // 2
    k_scanB_gemm1<<<NCHUNK + (NN + 31) / 32, 256>>>(x, W1, b1); // 3  <- ncu window
    k_fill<<<(EE + 255) / 256, 256>>>(ei);                    // 4
    k_gather<<<(NN * 32 + 255) / 256, 256>>>();               // 5
    k_final<<<(NN + 31) / 32, 256>>>(W20, W21, b2, Wl, bl, out); // 6
}

// round 5
// speedup vs baseline: 1.8639x; 1.5767x over previous
#include <cuda_runtime.h>

#define NN 50000
#define EE 800000
#define HH 64
#define CC 10
#define CHUNK 200
#define NCHUNK 250   // 250 * 200 = 50000

// Scratch (allocation-free: __device__ globals)
__device__ int g_stride;           // 1 if edge_index int32, 2 if int64 (low word)
__device__ int g_degi[NN];         // out-degree by src
__device__ int g_cnt[NN];          // in-degree by dst (CSR row lengths)
__device__ int g_rowstart[NN];     // CSR row offsets
__device__ int g_next[NN];         // fill cursors
__device__ int g_bsum[NCHUNK];
__device__ int g_srcs[EE];         // CSR column (src) indices grouped by dst
__device__ float g_dis[NN];
__device__ __align__(16) float g_h[NN * HH];
__device__ __align__(16) float g_hs[NN * HH];   // dis[i] * h[i]
__device__ __align__(16) float g_lap[NN * HH];

// ---------------------------------------------------------------------------
// Launch 0: dtype detect + zero histograms
// ---------------------------------------------------------------------------
__global__ __launch_bounds__(256) void k_pre(const int* __restrict__ p) {
    if (blockIdx.x == 0 && threadIdx.x < 32) {
        int t = threadIdx.x;
        int bad = (p[2 * t + 1] != 0);
        unsigned b = __ballot_sync(0xffffffffu, bad);
        if (t == 0) g_stride = (b == 0u) ? 2 : 1;
    }
    int i = blockIdx.x * 256 + threadIdx.x;
    int stride = gridDim.x * 256;
    for (int j = i; j < NN; j += stride) {
        g_degi[j] = 0;
        g_cnt[j] = 0;
    }
}

// ---------------------------------------------------------------------------
// Launch 1: src out-degree + dst in-degree
// ---------------------------------------------------------------------------
__global__ __launch_bounds__(256) void k_hist(const int* __restrict__ ei) {
    int e = blockIdx.x * 256 + threadIdx.x;
    if (e < EE) {
        int st = g_stride;
        int s = __ldg(&ei[e * st]);
        int d = __ldg(&ei[(EE + e) * st]);
        atomicAdd(&g_degi[s], 1);
        atomicAdd(&g_cnt[d], 1);
    }
}

// ---------------------------------------------------------------------------
// Launch 2: per-chunk sums of cnt -> g_bsum  +  dis = rsqrt(degi)
// ---------------------------------------------------------------------------
__global__ __launch_bounds__(256) void k_scanA() {
    __shared__ int sh[256];
    int t = threadIdx.x, b = blockIdx.x;
    int i = b * CHUNK + t;
    sh[t] = (t < CHUNK) ? g_cnt[i] : 0;
    __syncthreads();
#pragma unroll
    for (int off = 128; off > 0; off >>= 1) {
        if (t < off) sh[t] += sh[t + off];
        __syncthreads();
    }
    if (t == 0) g_bsum[b] = sh[0];
    if (t < CHUNK) {
        int d = g_degi[i];
        g_dis[i] = (d > 0) ? rsqrtf((float)d) : 0.f;
    }
}

// ---------------------------------------------------------------------------
// Launch 3 (fused): blocks [0,250): finish scan (rowstart/next)
//   blocks [250,...): register-tiled GEMM1: h = relu(x@W1+b1); hs = dis*h
//   128 rows/block; thread tile = 8 rows x 4 cols; 48 KB smem.
// ---------------------------------------------------------------------------
__global__ __launch_bounds__(256) void k_scanB_gemm1(const float* __restrict__ x,
                                                     const float* __restrict__ W1,
                                                     const float* __restrict__ b1) {
    __shared__ __align__(16) float sm[12288];   // 48 KB

    if (blockIdx.x < NCHUNK) {
        int* bs = (int*)sm;
        int* cs = bs + 256;
        int t = threadIdx.x, b = blockIdx.x;
        bs[t] = (t < NCHUNK) ? g_bsum[t] : 0;
        __syncthreads();
#pragma unroll
        for (int off = 1; off < 256; off <<= 1) {
            int add = (t >= off) ? bs[t - off] : 0;
            __syncthreads();
            bs[t] += add;
            __syncthreads();
        }
        int base = (b > 0) ? bs[b - 1] : 0;
        int i = b * CHUNK + t;
        int c = (t < CHUNK) ? g_cnt[i] : 0;
        cs[t] = c;
        __syncthreads();
#pragma unroll
        for (int off = 1; off < 256; off <<= 1) {
            int add = (t >= off) ? cs[t - off] : 0;
            __syncthreads();
            cs[t] += add;
            __syncthreads();
        }
        if (t < CHUNK) {
            int rs = base + cs[t] - c;
            g_rowstart[i] = rs;
            g_next[i] = rs;
        }
        return;
    }

    // ---- GEMM1 role ----
    float* Ws = sm;          // [64][64]
    float* xs = sm + 4096;   // [128][64]
    int tid = threadIdx.x;
    int rowbase = (blockIdx.x - NCHUNK) * 128;

    for (int i = tid; i < HH * HH; i += 256) Ws[i] = W1[i];
#pragma unroll
    for (int j = 0; j < 8; j++) {
        int idx = j * 256 + tid;           // float4 index (0..2047)
        int r = idx >> 4;
        int kq = (idx & 15) << 2;
        int grow = rowbase + r;
        float4 v = make_float4(0.f, 0.f, 0.f, 0.f);
        if (grow < NN) v = *(const float4*)&x[grow * HH + kq];
        *(float4*)&xs[r * HH + kq] = v;
    }
    __syncthreads();

    int tx = tid & 15, ty = tid >> 4;
    int c0 = tx * 4, r0 = ty * 8;
    float4 bv = *(const float4*)&b1[c0];
    float acc[8][4];
#pragma unroll
    for (int r = 0; r < 8; r++) {
        acc[r][0] = bv.x; acc[r][1] = bv.y; acc[r][2] = bv.z; acc[r][3] = bv.w;
    }

#pragma unroll 4
    for (int k = 0; k < HH; k += 2) {
        float4 wa = *(const float4*)&Ws[k * HH + c0];
        float4 wb = *(const float4*)&Ws[(k + 1) * HH + c0];
#pragma unroll
        for (int r = 0; r < 8; r++) {
            float2 xv = *(const float2*)&xs[(r0 + r) * HH + k];
            acc[r][0] = fmaf(xv.x, wa.x, acc[r][0]);
            acc[r][1] = fmaf(xv.x, wa.y, acc[r][1]);
            acc[r][2] = fmaf(xv.x, wa.z, acc[r][2]);
            acc[r][3] = fmaf(xv.x, wa.w, acc[r][3]);
            acc[r][0] = fmaf(xv.y, wb.x, acc[r][0]);
            acc[r][1] = fmaf(xv.y, wb.y, acc[r][1]);
            acc[r][2] = fmaf(xv.y, wb.z, acc[r][2]);
            acc[r][3] = fmaf(xv.y, wb.w, acc[r][3]);
        }
    }

#pragma unroll
    for (int r = 0; r < 8; r++) {
        int row = rowbase + r0 + r;
        if (row < NN) {
            float4 hv;
            hv.x = fmaxf(acc[r][0], 0.f);
            hv.y = fmaxf(acc[r][1], 0.f);
            hv.z = fmaxf(acc[r][2], 0.f);
            hv.w = fmaxf(acc[r][3], 0.f);
            float sc = __ldg(&g_dis[row]);
            *(float4*)&g_h[row * HH + c0] = hv;
            float4 sv = make_float4(sc * hv.x, sc * hv.y, sc * hv.z, sc * hv.w);
            *(float4*)&g_hs[row * HH + c0] = sv;
        }
    }
}

// ---------------------------------------------------------------------------
// Launch 4: bucket fill (group src indices by dst)
// ---------------------------------------------------------------------------
__global__ __launch_bounds__(256) void k_fill(const int* __restrict__ ei) {
    int e = blockIdx.x * 256 + threadIdx.x;
    if (e < EE) {
        int st = g_stride;
        int s = __ldg(&ei[e * st]);
        int d = __ldg(&ei[(EE + e) * st]);
        int pos = atomicAdd(&g_next[d], 1);
        g_srcs[pos] = s;
    }
}

// ---------------------------------------------------------------------------
// Launch 5: CSR gather  lap[d] = -dis[d] * sum hs[src]
// ---------------------------------------------------------------------------
__global__ __launch_bounds__(256) void k_gather() {
    int row = (blockIdx.x * 256 + threadIdx.x) >> 5;
    int lane = threadIdx.x & 31;
    if (row >= NN) return;

    int start = g_rowstart[row];
    int len = g_cnt[row];

    float ax = 0.f, ay = 0.f;
    for (int base = 0; base < len; base += 32) {
        int j = base + lane;
        int s = (j < len) ? __ldg(&g_srcs[start + j]) : 0;
        int m = min(32, len - base);
#pragma unroll 4
        for (int jj = 0; jj < m; jj++) {
            int sj = __shfl_sync(0xffffffffu, s, jj);
            float2 v = __ldg((const float2*)&g_hs[sj * HH + 2 * lane]);
            ax += v.x;
            ay += v.y;
        }
    }
    float sc = -g_dis[row];
    ((float2*)g_lap)[row * 32 + lane] = make_float2(ax * sc, ay * sc);
}

// ---------------------------------------------------------------------------
// Launch 6: fused conv2 + residual + linear + log_softmax.
//   Stage A: register-tiled dual GEMM  acc = h@W20 + lap@W21 + b2
//            (128 rows/block, thread tile 8x4, 96 KB dynamic smem)
//   Stage B: s = relu(acc)+h -> smem; logits p = s@Wl + bl
//   Stage C: per-row log_softmax -> out
// ---------------------------------------------------------------------------
__global__ __launch_bounds__(256) void k_final2(const float* __restrict__ W20,
                                                const float* __restrict__ W21,
                                                const float* __restrict__ b2,
                                                const float* __restrict__ Wl,
                                                const float* __restrict__ bl,
                                                float* __restrict__ out) {
    extern __shared__ float dsm[];
    float* W20s = dsm;             // [64][64]  (reused for Wl in epilogue)
    float* W21s = dsm + 4096;      // [64][64]  (reused for pbuf in epilogue)
    float* hsm  = dsm + 8192;      // [128][64]
    float* lsm  = dsm + 16384;     // [128][64] (reused for s in epilogue)

    int tid = threadIdx.x;
    int rowbase = blockIdx.x * 128;

    for (int i = tid; i < HH * HH; i += 256) {
        W20s[i] = W20[i];
        W21s[i] = W21[i];
    }
#pragma unroll
    for (int j = 0; j < 16; j++) {
        int idx = j * 256 + tid;           // float4 index (0..4095)
        int r = (idx >> 4) & 127;
        int half = idx >> 11;              // 0: h, 1: lap
        int kq = (idx & 15) << 2;
        int grow = rowbase + r;
        float4 v = make_float4(0.f, 0.f, 0.f, 0.f);
        if (grow < NN) {
            const float* srcp = half ? &g_lap[grow * HH + kq] : &g_h[grow * HH + kq];
            v = *(const float4*)srcp;
        }
        float* dstp = half ? &lsm[r * HH + kq] : &hsm[r * HH + kq];
        *(float4*)dstp = v;
    }
    __syncthreads();

    int tx = tid & 15, ty = tid >> 4;
    int c0 = tx * 4, r0 = ty * 8;
    float4 b2v = *(const float4*)&b2[c0];
    float acc[8][4];
#pragma unroll
    for (int r = 0; r < 8; r++) {
        acc[r][0] = b2v.x; acc[r][1] = b2v.y; acc[r][2] = b2v.z; acc[r][3] = b2v.w;
    }

#pragma unroll 2
    for (int k = 0; k < HH; k += 2) {
        float4 wa0 = *(const float4*)&W20s[k * HH + c0];
        float4 wa1 = *(const float4*)&W20s[(k + 1) * HH + c0];
        float4 wb0 = *(const float4*)&W21s[k * HH + c0];
        float4 wb1 = *(const float4*)&W21s[(k + 1) * HH + c0];
#pragma unroll
        for (int r = 0; r < 8; r++) {
            float2 hv = *(const float2*)&hsm[(r0 + r) * HH + k];
            float2 lv = *(const float2*)&lsm[(r0 + r) * HH + k];
            acc[r][0] = fmaf(hv.x, wa0.x, acc[r][0]);
            acc[r][1] = fmaf(hv.x, wa0.y, acc[r][1]);
            acc[r][2] = fmaf(hv.x, wa0.z, acc[r][2]);
            acc[r][3] = fmaf(hv.x, wa0.w, acc[r][3]);
            acc[r][0] = fmaf(hv.y, wa1.x, acc[r][0]);
            acc[r][1] = fmaf(hv.y, wa1.y, acc[r][1]);
            acc[r][2] = fmaf(hv.y, wa1.z, acc[r][2]);
            acc[r][3] = fmaf(hv.y, wa1.w, acc[r][3]);
            acc[r][0] = fmaf(lv.x, wb0.x, acc[r][0]);
            acc[r][1] = fmaf(lv.x, wb0.y, acc[r][1]);
            acc[r][2] = fmaf(lv.x, wb0.z, acc[r][2]);
            acc[r][3] = fmaf(lv.x, wb0.w, acc[r][3]);
            acc[r][0] = fmaf(lv.y, wb1.x, acc[r][0]);
            acc[r][1] = fmaf(lv.y, wb1.y, acc[r][1]);
            acc[r][2] = fmaf(lv.y, wb1.z, acc[r][2]);
            acc[r][3] = fmaf(lv.y, wb1.w, acc[r][3]);
        }
    }
    __syncthreads();   // all main-loop smem reads complete

    // s = relu(acc) + h  -> lsm ;  load Wl into W20s region
#pragma unroll
    for (int r = 0; r < 8; r++) {
        float4 hv = *(const float4*)&hsm[(r0 + r) * HH + c0];
        float4 sv;
        sv.x = fmaxf(acc[r][0], 0.f) + hv.x;
        sv.y = fmaxf(acc[r][1], 0.f) + hv.y;
        sv.z = fmaxf(acc[r][2], 0.f) + hv.z;
        sv.w = fmaxf(acc[r][3], 0.f) + hv.w;
        *(float4*)&lsm[(r0 + r) * HH + c0] = sv;
    }
    for (int i = tid; i < HH * CC; i += 256) W20s[i] = Wl[i];
    __syncthreads();

    // Stage B: logits  pbuf[r][c] = s[r] . Wl[:,c] + bl[c]
    float* pbuf = W21s;
    for (int o = tid; o < 128 * CC; o += 256) {
        int r = o / CC, c = o - r * CC;
        float a = __ldg(&bl[c]);
        const float* srow = &lsm[r * HH];
#pragma unroll
        for (int k = 0; k < HH; k++) a = fmaf(srow[k], W20s[k * CC + c], a);
        pbuf[o] = a;
    }
    __syncthreads();

    // Stage C: log_softmax per row
    if (tid < 128) {
        int row = rowbase + tid;
        if (row < NN) {
            float p[CC];
            float m = -1e30f;
#pragma unroll
            for (int c = 0; c < CC; c++) {
                p[c] = pbuf[tid * CC + c];
                m = fmaxf(m, p[c]);
            }
            float sum = 0.f;
#pragma unroll
            for (int c = 0; c < CC; c++) sum += expf(p[c] - m);
            float lse = logf(sum);
#pragma unroll
            for (int c = 0; c < CC; c++) out[row * CC + c] = p[c] - m - lse;
        }
    }
}

// ---------------------------------------------------------------------------
extern "C" void kernel_launch(void* const* d_in, const int* in_sizes, int n_in,
                              void* d_out, int out_size) {
    const float* x   = (const float*)d_in[0];
    const int*   ei  = (const int*)d_in[1];
    const float* W1  = (const float*)d_in[2];
    const float* b1  = (const float*)d_in[3];
    const float* W20 = (const float*)d_in[4];
    const float* W21 = (const float*)d_in[5];
    const float* b2  = (const float*)d_in[6];
    const float* Wl  = (const float*)d_in[7];
    const float* bl  = (const float*)d_in[8];
    float* out = (float*)d_out;

    static int smem_set = 0;
    if (!smem_set) {
        cudaFuncSetAttribute(k_final2, cudaFuncAttributeMaxDynamicSharedMemorySize, 98304);
        smem_set = 1;
    }

    const int GB = (NN + 127) / 128;   // 391 gemm blocks

    k_pre<<<64, 256>>>(ei);                                     // 0
    k_hist<<<(EE + 255) / 256, 256>>>(ei);                      // 1
    k_scanA<<<NCHUNK, 256>>>();                                 // 2
    k_scanB_gemm1<<<NCHUNK + GB, 256>>>(x, W1, b1);             // 3  <- ncu window
    k_fill<<<(EE + 255) / 256, 256>>>(ei);                      // 4
    k_gather<<<(NN * 32 + 255) / 256, 256>>>();                 // 5
    k_final2<<<GB, 256, 98304>>>(W20, W21, b2, Wl, bl, out);    // 6
}